// round 12
// baseline (speedup 1.0000x reference)
#include <cuda_runtime.h>
#include <cuda_fp16.h>

#define B_   4
#define LQ_  128
#define LK_  256
#define D_   128
#define H_   128
#define NH_  8

#define L2E 1.4426950408889634f  // log2(e) for softmax exp

#define NPART 8                  // one output-projection partial per head

// ---- scratch (static device memory; no allocation) ----
__device__ __align__(16) float  g_QH[B_*NH_*H_*LQ_];      // [b][n][h][q] fp32
__device__ __align__(16) __half g_KHh[B_*NH_*H_*LK_];     // [b][n][h][k] fp16
__device__ __align__(16) float  g_PART[NPART*B_*LQ_*H_];  // per-head outproj partials

// ============================================================================
// K1: merged Q+K per-head projections  (round-9 exact)
// OUT[b][n][h][l] = sum_d W[n][h][d] * X[b][l][d]
// 64x64 tile, BK=16, 256 threads, 4x4 per thread.
// grid = (4, 2, 64); z<32 -> K-proj (fp16 out), z>=32 -> Q-proj (fp32 out).
// ============================================================================
__global__ void __launch_bounds__(256) proj_kernel(
    const float* __restrict__ Q, const float* __restrict__ K,
    const float* __restrict__ Wq, const float* __restrict__ Wk)
{
    int zz = blockIdx.z;
    bool isq = zz >= 32;
    int bn = isq ? (zz - 32) : zz;
    int b = bn >> 3, n = bn & 7;
    int L = isq ? LQ_ : LK_;
    int l0 = blockIdx.x * 64;
    if (l0 >= L) return;                        // uniform per block
    const float* X = isq ? Q : K;
    const float* W = isq ? Wq : Wk;

    __shared__ float Ws[16][64];   // [d][h]
    __shared__ float Xs[16][64];   // [d][l]
    int h0 = blockIdx.y * 64;
    int tid = threadIdx.x;                 // 256
    int ty = tid >> 4, tx = tid & 15;      // 16x16
    float acc[4][4] = {};
    const float* Wp = W + (n*H_ + h0)*D_;
    const float* Xp = X + (b*L  + l0)*D_;
    int row = tid >> 2;          // 0..63
    int dq  = (tid & 3) * 4;     // 0,4,8,12
    for (int d0 = 0; d0 < D_; d0 += 16) {
        float4 w4 = *(const float4*)(Wp + row*D_ + d0 + dq);
        float4 x4 = *(const float4*)(Xp + row*D_ + d0 + dq);
        __syncthreads();
        Ws[dq+0][row] = w4.x; Ws[dq+1][row] = w4.y; Ws[dq+2][row] = w4.z; Ws[dq+3][row] = w4.w;
        Xs[dq+0][row] = x4.x; Xs[dq+1][row] = x4.y; Xs[dq+2][row] = x4.z; Xs[dq+3][row] = x4.w;
        __syncthreads();
        #pragma unroll
        for (int dd = 0; dd < 16; ++dd) {
            float4 a4 = *(const float4*)&Ws[dd][ty*4];
            float4 b4 = *(const float4*)&Xs[dd][tx*4];
            float av[4] = {a4.x, a4.y, a4.z, a4.w};
            float bv[4] = {b4.x, b4.y, b4.z, b4.w};
            #pragma unroll
            for (int i = 0; i < 4; ++i)
                #pragma unroll
                for (int j = 0; j < 4; ++j)
                    acc[i][j] = fmaf(av[i], bv[j], acc[i][j]);
        }
    }
    if (isq) {
        float* Op = g_QH + ((b*NH_ + n)*H_ + h0 + ty*4)*L + l0 + tx*4;
        #pragma unroll
        for (int i = 0; i < 4; ++i)
            *(float4*)(Op + i*L) = make_float4(acc[i][0], acc[i][1], acc[i][2], acc[i][3]);
    } else {
        __half* Op = g_KHh + ((b*NH_ + n)*H_ + h0 + ty*4)*LK_ + l0 + tx*4;
        #pragma unroll
        for (int i = 0; i < 4; ++i) {
            __half2 h01 = __floats2half2_rn(acc[i][0], acc[i][1]);
            __half2 h23 = __floats2half2_rn(acc[i][2], acc[i][3]);
            *(__half2*)(Op + i*LK_)     = h01;
            *(__half2*)(Op + i*LK_ + 2) = h23;
        }
    }
}

// ============================================================================
// K2: FUSED scores + masked softmax + attn@V + per-head output projection.
// Phases 0-2 are round-9 exact (best measured). New epilogue: project the
// block's 8q x 128d head-output through Wo[:, n*D:(n+1)*D] (staged in smem,
// reusing the Vs buffer) into g_PART[n] — replaces the split-K outproj kernel
// and the g_CONCAT round-trip.
// ============================================================================
__global__ void __launch_bounds__(256) score_av_kernel(
    const float* __restrict__ wv, const int* __restrict__ valid_lens,
    const float* __restrict__ V, const float* __restrict__ Wo)
{
    __shared__ __half Ks[16][LK_];     // [h][k] fp16   8KB
    __shared__ float Qs[16][8];        // [h][q]
    __shared__ float Wvs[16];
    __shared__ float redA[2][4][4];
    __shared__ float redB[2][4][4];
    __shared__ float attn_s[8][LK_];   // [q][k]        8KB
    __shared__ float Vs[32][D_];       // [k][d]       16KB (reused for Wo chunks)
    __shared__ float oa_s[8][D_];      // [q][d]        4KB head output

    int b = blockIdx.z, n = blockIdx.y;
    int q0 = blockIdx.x * 8;
    int tid = threadIdx.x;
    int qg = tid >> 7;      // 0..1
    int kg = tid & 127;     // 0..127
    int ks = kg * 2;
    int valid = valid_lens[b];
    bool active = ks < valid;
    const __half* KHp = g_KHh + ((b*NH_ + n)*H_)*LK_;
    const float*  QHp = g_QH  + ((b*NH_ + n)*H_)*LQ_ + q0;
    const float*  wvp = wv + n*H_;

    float acc[4][2] = {};

    for (int h0 = 0; h0 < H_; h0 += 16) {
        __syncthreads();
        #pragma unroll
        for (int t = 0; t < 2; ++t) {               // stage K chunk [16h][256k] fp16
            int idx = tid + t*256;                  // 512 uint4 (8 halves each)
            int r = idx >> 5, c = idx & 31;
            *(uint4*)&Ks[r][c*8] = *(const uint4*)(KHp + (h0+r)*LK_ + c*8);
        }
        if (tid < 128) Qs[tid >> 3][tid & 7] = QHp[(h0 + (tid >> 3))*LQ_ + (tid & 7)];
        if (tid < 16) Wvs[tid] = wvp[h0 + tid];
        __syncthreads();

        if (active) {
            #pragma unroll
            for (int dd = 0; dd < 16; ++dd) {
                unsigned k2u = *(const unsigned*)&Ks[dd][ks];
                float4 q4 = *(const float4*)&Qs[dd][qg*4];
                float w = Wvs[dd];
                float qv[4] = {q4.x, q4.y, q4.z, q4.w};
                #pragma unroll
                for (int i = 0; i < 4; ++i) {
                    unsigned qh, su, tu;
                    asm("cvt.rn.f16x2.f32 %0, %1, %2;" : "=r"(qh) : "f"(qv[i]), "f"(qv[i]));
                    asm("add.rn.f16x2 %0, %1, %2;"     : "=r"(su) : "r"(qh), "r"(k2u));
                    asm("tanh.approx.f16x2 %0, %1;"    : "=r"(tu) : "r"(su));
                    __half2 th = *reinterpret_cast<__half2*>(&tu);
                    float2 f = __half22float2(th);
                    acc[i][0] = fmaf(w, f.x, acc[i][0]);
                    acc[i][1] = fmaf(w, f.y, acc[i][1]);
                }
            }
        }
    }

    // ---- softmax over k (4 warps per q-group) ----
    float m[4];
    #pragma unroll
    for (int i = 0; i < 4; ++i) {
        float mm = -1e30f;
        #pragma unroll
        for (int j = 0; j < 2; ++j)
            if (ks + j < valid) mm = fmaxf(mm, acc[i][j]);
        m[i] = mm;
    }
    #pragma unroll
    for (int off = 16; off; off >>= 1)
        #pragma unroll
        for (int i = 0; i < 4; ++i)
            m[i] = fmaxf(m[i], __shfl_xor_sync(0xffffffffu, m[i], off));
    int w4 = (tid >> 5) & 3;
    if ((tid & 31) == 0)
        #pragma unroll
        for (int i = 0; i < 4; ++i) redA[qg][w4][i] = m[i];
    __syncthreads();
    #pragma unroll
    for (int i = 0; i < 4; ++i)
        m[i] = fmaxf(fmaxf(redA[qg][0][i], redA[qg][1][i]),
                     fmaxf(redA[qg][2][i], redA[qg][3][i]));

    float p[4][2], s[4] = {0.f, 0.f, 0.f, 0.f};
    #pragma unroll
    for (int i = 0; i < 4; ++i)
        #pragma unroll
        for (int j = 0; j < 2; ++j) {
            float e;
            asm("ex2.approx.f32 %0, %1;" : "=f"(e) : "f"((acc[i][j] - m[i]) * L2E));
            bool v = (ks + j) < valid;
            p[i][j] = v ? e : 0.0f;
            s[i] += p[i][j];
        }
    #pragma unroll
    for (int off = 16; off; off >>= 1)
        #pragma unroll
        for (int i = 0; i < 4; ++i)
            s[i] += __shfl_xor_sync(0xffffffffu, s[i], off);
    if ((tid & 31) == 0)
        #pragma unroll
        for (int i = 0; i < 4; ++i) redB[qg][w4][i] = s[i];
    __syncthreads();

    #pragma unroll
    for (int i = 0; i < 4; ++i) {
        float inv = 1.0f / (redB[qg][0][i] + redB[qg][1][i] +
                            redB[qg][2][i] + redB[qg][3][i]);
        *(float2*)&attn_s[qg*4+i][ks] = make_float2(p[i][0]*inv, p[i][1]*inv);
    }
    // (attn_s fully written for k in [0,256): zeros beyond valid)

    // ---- Phase 2: out = attn_s @ V[b], thread = 1q x 4d ----
    int ty = tid >> 5;          // q row 0..7
    int tx = tid & 31;          // d group of 4
    float oa[4] = {};
    int kend = (valid + 31) & ~31;
    const float* Vp = V + (b*LK_)*D_;
    for (int k0 = 0; k0 < kend; k0 += 32) {
        __syncthreads();        // also orders attn_s writes on first iter
        #pragma unroll
        for (int t = 0; t < 4; ++t) {   // stage V chunk [32k][128d]
            int idx = tid + t*256;
            int r = idx >> 5, c4 = idx & 31;
            *(float4*)&Vs[r][c4*4] = *(const float4*)(Vp + (k0+r)*D_ + c4*4);
        }
        __syncthreads();
        #pragma unroll
        for (int kk = 0; kk < 32; ++kk) {
            float a = attn_s[ty][k0+kk];          // broadcast within warp
            float4 v4 = *(const float4*)&Vs[kk][tx*4];
            oa[0] = fmaf(a, v4.x, oa[0]);
            oa[1] = fmaf(a, v4.y, oa[1]);
            oa[2] = fmaf(a, v4.z, oa[2]);
            oa[3] = fmaf(a, v4.w, oa[3]);
        }
    }

    // ---- Epilogue: per-head output projection partial ----
    // g_PART[n][b*LQ+q0+q][h] = sum_d oa_s[q][d] * Wo[h][n*D+d]
    *(float4*)&oa_s[ty][tx*4] = make_float4(oa[0], oa[1], oa[2], oa[3]);
    {
        float* wbuf = (float*)Vs;      // reuse as [32h][128d] Wo chunk (16KB)
        int q  = tid >> 5;             // 0..7
        int hl = tid & 31;             // 0..31
        #pragma unroll
        for (int c = 0; c < 4; ++c) {
            __syncthreads();           // c==0: oa_s visible + last Vs reads done
            #pragma unroll
            for (int t = 0; t < 4; ++t) {
                int idx = tid + t*256;             // 1024 float4s
                int hr = idx >> 5, c4 = idx & 31;
                *(float4*)&wbuf[hr*D_ + c4*4] =
                    *(const float4*)(Wo + (c*32 + hr)*(NH_*D_) + n*D_ + c4*4);
            }
            __syncthreads();
            float acc2 = 0.f;
            #pragma unroll
            for (int j = 0; j < 32; ++j) {
                int c4 = (j + hl) & 31;            // lane-rotated: conflict-free
                float4 a4 = *(const float4*)&oa_s[q][c4*4];
                float4 w4v = *(const float4*)&wbuf[hl*D_ + c4*4];
                acc2 = fmaf(a4.x, w4v.x, fmaf(a4.y, w4v.y,
                       fmaf(a4.z, w4v.z, fmaf(a4.w, w4v.w, acc2))));
            }
            g_PART[((n*B_ + b)*LQ_ + q0 + q)*H_ + c*32 + hl] = acc2;
        }
    }
}

// ============================================================================
// K3: reduce head partials + bias.  out[r][h] = bias[h] + sum_n part[n][r][h]
// 16384 threads, float4 each. Deterministic (fixed summation order).
// ============================================================================
__global__ void __launch_bounds__(256) outproj_reduce_kernel(
    const float* __restrict__ bias, float* __restrict__ out)
{
    int idx = blockIdx.x * 256 + threadIdx.x;     // float4 index over 512*128/4
    int h4 = (idx & (H_/4 - 1)) * 4;
    float4 a = *(const float4*)(bias + h4);
    #pragma unroll
    for (int s = 0; s < NPART; ++s) {
        float4 p = *(const float4*)(g_PART + s*(B_*LQ_*H_) + idx*4);
        a.x += p.x; a.y += p.y; a.z += p.z; a.w += p.w;
    }
    *(float4*)((float*)out + idx*4) = a;
}

// ============================================================================
extern "C" void kernel_launch(void* const* d_in, const int* in_sizes, int n_in,
                              void* d_out, int out_size)
{
    const float* queries    = (const float*)d_in[0];
    const float* keys       = (const float*)d_in[1];
    const float* values     = (const float*)d_in[2];
    const int*   valid_lens = (const int*)  d_in[3];
    const float* Wq         = (const float*)d_in[4];
    const float* Wk         = (const float*)d_in[5];
    const float* wv         = (const float*)d_in[6];
    const float* Wo_w       = (const float*)d_in[7];
    const float* Wo_b       = (const float*)d_in[8];
    float* out = (float*)d_out;

    proj_kernel<<<dim3(4, 2, 64), 256>>>(queries, keys, Wq, Wk);
    score_av_kernel<<<dim3(LQ_/8, NH_, B_), 256>>>(wv, valid_lens, values, Wo_w);
    outproj_reduce_kernel<<<dim3(B_*LQ_*H_/4/256), 256>>>(Wo_b, out);
}

// round 13
// speedup vs baseline: 1.1791x; 1.1791x over previous
#include <cuda_runtime.h>
#include <cuda_fp16.h>

#define B_   4
#define LQ_  128
#define LK_  256
#define D_   128
#define H_   128
#define NH_  8

#define L2E 1.4426950408889634f  // log2(e) for softmax exp

#define NSPLIT 8                 // K-splits for the output projection

// ---- scratch (static device memory; no allocation) ----
__device__ __align__(16) float  g_QH[B_*NH_*H_*LQ_];      // [b][n][h][q] fp32
__device__ __align__(16) __half g_KHh[B_*NH_*H_*LK_];     // [b][n][h][k] fp16
__device__ __align__(16) float  g_CONCAT[B_*LQ_*NH_*D_];  // [b][q][n*D+d]
__device__ __align__(16) float  g_PART[NSPLIT*B_*LQ_*H_]; // split-K partials

// ============================================================================
// K1: merged Q+K per-head projections — double-buffered smem.
// OUT[b][n][h][l] = sum_d W[n][h][d] * X[b][l][d]
// 64x64 tile, BK=16, 256 threads, 4x4 per thread; ONE barrier per BK chunk
// (prefetch next chunk to registers before the barrier, ping-pong buffers).
// grid = (4, 2, 64); z<32 -> K-proj (fp16 out), z>=32 -> Q-proj (fp32 out).
// ============================================================================
__global__ void __launch_bounds__(256) proj_kernel(
    const float* __restrict__ Q, const float* __restrict__ K,
    const float* __restrict__ Wq, const float* __restrict__ Wk)
{
    int zz = blockIdx.z;
    bool isq = zz >= 32;
    int bn = isq ? (zz - 32) : zz;
    int b = bn >> 3, n = bn & 7;
    int L = isq ? LQ_ : LK_;
    int l0 = blockIdx.x * 64;
    if (l0 >= L) return;                        // uniform per block
    const float* X = isq ? Q : K;
    const float* W = isq ? Wq : Wk;

    __shared__ float Ws[2][16][64];   // [buf][d][h]  16KB
    __shared__ float Xs[2][16][64];   // [buf][d][l]  16KB
    int h0 = blockIdx.y * 64;
    int tid = threadIdx.x;                 // 256
    int ty = tid >> 4, tx = tid & 15;      // 16x16
    float acc[4][4] = {};
    const float* Wp = W + (n*H_ + h0)*D_;
    const float* Xp = X + (b*L  + l0)*D_;
    int row = tid >> 2;          // 0..63
    int dq  = (tid & 3) * 4;     // 0,4,8,12

    float4 w4 = *(const float4*)(Wp + row*D_ + dq);
    float4 x4 = *(const float4*)(Xp + row*D_ + dq);
    #pragma unroll
    for (int c = 0; c < 8; ++c) {
        int buf = c & 1;
        Ws[buf][dq+0][row] = w4.x; Ws[buf][dq+1][row] = w4.y;
        Ws[buf][dq+2][row] = w4.z; Ws[buf][dq+3][row] = w4.w;
        Xs[buf][dq+0][row] = x4.x; Xs[buf][dq+1][row] = x4.y;
        Xs[buf][dq+2][row] = x4.z; Xs[buf][dq+3][row] = x4.w;
        if (c < 7) {
            w4 = *(const float4*)(Wp + row*D_ + (c+1)*16 + dq);
            x4 = *(const float4*)(Xp + row*D_ + (c+1)*16 + dq);
        }
        __syncthreads();
        #pragma unroll
        for (int dd = 0; dd < 16; ++dd) {
            float4 a4 = *(const float4*)&Ws[buf][dd][ty*4];
            float4 b4 = *(const float4*)&Xs[buf][dd][tx*4];
            float av[4] = {a4.x, a4.y, a4.z, a4.w};
            float bv[4] = {b4.x, b4.y, b4.z, b4.w};
            #pragma unroll
            for (int i = 0; i < 4; ++i)
                #pragma unroll
                for (int j = 0; j < 4; ++j)
                    acc[i][j] = fmaf(av[i], bv[j], acc[i][j]);
        }
    }
    if (isq) {
        float* Op = g_QH + ((b*NH_ + n)*H_ + h0 + ty*4)*L + l0 + tx*4;
        #pragma unroll
        for (int i = 0; i < 4; ++i)
            *(float4*)(Op + i*L) = make_float4(acc[i][0], acc[i][1], acc[i][2], acc[i][3]);
    } else {
        __half* Op = g_KHh + ((b*NH_ + n)*H_ + h0 + ty*4)*LK_ + l0 + tx*4;
        #pragma unroll
        for (int i = 0; i < 4; ++i) {
            __half2 h01 = __floats2half2_rn(acc[i][0], acc[i][1]);
            __half2 h23 = __floats2half2_rn(acc[i][2], acc[i][3]);
            *(__half2*)(Op + i*LK_)     = h01;
            *(__half2*)(Op + i*LK_ + 2) = h23;
        }
    }
}

// ============================================================================
// K2: FUSED scores + masked softmax + attn@V.  (round-9 exact — best measured)
// Block = (b, n, 8 q-rows). Phase 1: thread = 4q x 2k; k-pair is a half2 —
// tanh.approx.f16x2 does 2 tanh per MUFU op; accumulate in fp32.
// Phase 2: thread = 1q x 4d over V chunks; writes concat layout directly.
// k >= valid_len contributes exactly 0 (softmax mask).
// ============================================================================
__global__ void __launch_bounds__(256) score_av_kernel(
    const float* __restrict__ wv, const int* __restrict__ valid_lens,
    const float* __restrict__ V)
{
    __shared__ __half Ks[16][LK_];     // [h][k] fp16  8KB
    __shared__ float Qs[16][8];        // [h][q]
    __shared__ float Wvs[16];
    __shared__ float redA[2][4][4];
    __shared__ float redB[2][4][4];
    __shared__ float attn_s[8][LK_];   // [q][k]   8KB
    __shared__ float Vs[32][D_];       // [k][d]  16KB

    int b = blockIdx.z, n = blockIdx.y;
    int q0 = blockIdx.x * 8;
    int tid = threadIdx.x;
    int qg = tid >> 7;      // 0..1
    int kg = tid & 127;     // 0..127
    int ks = kg * 2;
    int valid = valid_lens[b];
    bool active = ks < valid;
    const __half* KHp = g_KHh + ((b*NH_ + n)*H_)*LK_;
    const float*  QHp = g_QH  + ((b*NH_ + n)*H_)*LQ_ + q0;
    const float*  wvp = wv + n*H_;

    float acc[4][2] = {};

    for (int h0 = 0; h0 < H_; h0 += 16) {
        __syncthreads();
        #pragma unroll
        for (int t = 0; t < 2; ++t) {               // stage K chunk [16h][256k] fp16
            int idx = tid + t*256;                  // 512 uint4 (8 halves each)
            int r = idx >> 5, c = idx & 31;
            *(uint4*)&Ks[r][c*8] = *(const uint4*)(KHp + (h0+r)*LK_ + c*8);
        }
        if (tid < 128) Qs[tid >> 3][tid & 7] = QHp[(h0 + (tid >> 3))*LQ_ + (tid & 7)];
        if (tid < 16) Wvs[tid] = wvp[h0 + tid];
        __syncthreads();

        if (active) {
            #pragma unroll
            for (int dd = 0; dd < 16; ++dd) {
                unsigned k2u = *(const unsigned*)&Ks[dd][ks];
                float4 q4 = *(const float4*)&Qs[dd][qg*4];
                float w = Wvs[dd];
                float qv[4] = {q4.x, q4.y, q4.z, q4.w};
                #pragma unroll
                for (int i = 0; i < 4; ++i) {
                    unsigned qh, su, tu;
                    asm("cvt.rn.f16x2.f32 %0, %1, %2;" : "=r"(qh) : "f"(qv[i]), "f"(qv[i]));
                    asm("add.rn.f16x2 %0, %1, %2;"     : "=r"(su) : "r"(qh), "r"(k2u));
                    asm("tanh.approx.f16x2 %0, %1;"    : "=r"(tu) : "r"(su));
                    __half2 th = *reinterpret_cast<__half2*>(&tu);
                    float2 f = __half22float2(th);
                    acc[i][0] = fmaf(w, f.x, acc[i][0]);
                    acc[i][1] = fmaf(w, f.y, acc[i][1]);
                }
            }
        }
    }

    // ---- softmax over k (4 warps per q-group) ----
    float m[4];
    #pragma unroll
    for (int i = 0; i < 4; ++i) {
        float mm = -1e30f;
        #pragma unroll
        for (int j = 0; j < 2; ++j)
            if (ks + j < valid) mm = fmaxf(mm, acc[i][j]);
        m[i] = mm;
    }
    #pragma unroll
    for (int off = 16; off; off >>= 1)
        #pragma unroll
        for (int i = 0; i < 4; ++i)
            m[i] = fmaxf(m[i], __shfl_xor_sync(0xffffffffu, m[i], off));
    int w4 = (tid >> 5) & 3;
    if ((tid & 31) == 0)
        #pragma unroll
        for (int i = 0; i < 4; ++i) redA[qg][w4][i] = m[i];
    __syncthreads();
    #pragma unroll
    for (int i = 0; i < 4; ++i)
        m[i] = fmaxf(fmaxf(redA[qg][0][i], redA[qg][1][i]),
                     fmaxf(redA[qg][2][i], redA[qg][3][i]));

    float p[4][2], s[4] = {0.f, 0.f, 0.f, 0.f};
    #pragma unroll
    for (int i = 0; i < 4; ++i)
        #pragma unroll
        for (int j = 0; j < 2; ++j) {
            float e;
            asm("ex2.approx.f32 %0, %1;" : "=f"(e) : "f"((acc[i][j] - m[i]) * L2E));
            bool v = (ks + j) < valid;
            p[i][j] = v ? e : 0.0f;
            s[i] += p[i][j];
        }
    #pragma unroll
    for (int off = 16; off; off >>= 1)
        #pragma unroll
        for (int i = 0; i < 4; ++i)
            s[i] += __shfl_xor_sync(0xffffffffu, s[i], off);
    if ((tid & 31) == 0)
        #pragma unroll
        for (int i = 0; i < 4; ++i) redB[qg][w4][i] = s[i];
    __syncthreads();

    #pragma unroll
    for (int i = 0; i < 4; ++i) {
        float inv = 1.0f / (redB[qg][0][i] + redB[qg][1][i] +
                            redB[qg][2][i] + redB[qg][3][i]);
        *(float2*)&attn_s[qg*4+i][ks] = make_float2(p[i][0]*inv, p[i][1]*inv);
    }
    // (attn_s fully written for k in [0,256): zeros beyond valid)

    // ---- Phase 2: out = attn_s @ V[b], thread = 1q x 4d ----
    int ty = tid >> 5;          // q row 0..7
    int tx = tid & 31;          // d group of 4
    float oa[4] = {};
    int kend = (valid + 31) & ~31;
    const float* Vp = V + (b*LK_)*D_;
    for (int k0 = 0; k0 < kend; k0 += 32) {
        __syncthreads();        // also orders attn_s writes on first iter
        #pragma unroll
        for (int t = 0; t < 4; ++t) {   // stage V chunk [32k][128d]
            int idx = tid + t*256;
            int r = idx >> 5, c4 = idx & 31;
            *(float4*)&Vs[r][c4*4] = *(const float4*)(Vp + (k0+r)*D_ + c4*4);
        }
        __syncthreads();
        #pragma unroll
        for (int kk = 0; kk < 32; ++kk) {
            float a = attn_s[ty][k0+kk];          // broadcast within warp
            float4 v4 = *(const float4*)&Vs[kk][tx*4];
            oa[0] = fmaf(a, v4.x, oa[0]);
            oa[1] = fmaf(a, v4.y, oa[1]);
            oa[2] = fmaf(a, v4.z, oa[2]);
            oa[3] = fmaf(a, v4.w, oa[3]);
        }
    }
    float* Cp = g_CONCAT + (b*LQ_ + q0 + ty)*(NH_*D_) + n*D_ + tx*4;
    *(float4*)Cp = make_float4(oa[0], oa[1], oa[2], oa[3]);
}

// ============================================================================
// K3a: split-K output projection partials.  (round-9 exact)
// grid (8 row-tiles, 4 h-tiles, 8 splits), 256 threads.
// Tile: 64 rows x 32 h, K-chunk = 128 per split, BK=16 -> 8 iterations.
// Bs rows 144B (16B multiple) for aligned float4 reads.
// ============================================================================
__global__ void __launch_bounds__(256) outproj_split_kernel(
    const float* __restrict__ Wo)
{
    __shared__ float As[16][65];   // [j][row] (scalar-read only)
    __shared__ float Bs[16][36];   // [j][h]   (float4-read, 16B-aligned rows)
    int r0 = blockIdx.x * 64;
    int h0 = blockIdx.y * 32;
    int split = blockIdx.z;
    int j0base = split * (NH_*D_ / NSPLIT);   // 128-wide K chunk
    int tid = threadIdx.x;          // 256
    int ry = tid >> 3;              // 0..31 -> row pair
    int tx = tid & 7;               // -> h group of 4
    const float* Cc = g_CONCAT;
    float acc[2][4] = {};

    int arow = tid >> 2;            // 0..63 (A staging row)
    int ajq  = (tid & 3) * 4;       // j offset 0,4,8,12
    int bhr  = (tid & 127) >> 2;    // 0..31 (B staging h), threads 0..127 only
    int bjq  = (tid & 3) * 4;

    #pragma unroll
    for (int jc = 0; jc < 8; ++jc) {
        int j0 = j0base + jc * 16;
        __syncthreads();
        {
            float4 a = *(const float4*)(Cc + (r0+arow)*(NH_*D_) + j0 + ajq);
            As[ajq+0][arow] = a.x; As[ajq+1][arow] = a.y;
            As[ajq+2][arow] = a.z; As[ajq+3][arow] = a.w;
        }
        if (tid < 128) {
            float4 w = *(const float4*)(Wo + (h0+bhr)*(NH_*D_) + j0 + bjq);
            Bs[bjq+0][bhr] = w.x; Bs[bjq+1][bhr] = w.y;
            Bs[bjq+2][bhr] = w.z; Bs[bjq+3][bhr] = w.w;
        }
        __syncthreads();
        #pragma unroll
        for (int jj = 0; jj < 16; ++jj) {
            float a0 = As[jj][ry*2+0];
            float a1 = As[jj][ry*2+1];
            float4 b4 = *(const float4*)&Bs[jj][tx*4];
            float bv[4] = {b4.x, b4.y, b4.z, b4.w};
            #pragma unroll
            for (int j = 0; j < 4; ++j) {
                acc[0][j] = fmaf(a0, bv[j], acc[0][j]);
                acc[1][j] = fmaf(a1, bv[j], acc[1][j]);
            }
        }
    }
    float* Pp = g_PART + ((split*(B_*LQ_)) + r0 + ry*2)*H_ + h0 + tx*4;
    #pragma unroll
    for (int i = 0; i < 2; ++i)
        *(float4*)(Pp + i*H_) = make_float4(acc[i][0], acc[i][1], acc[i][2], acc[i][3]);
}

// ============================================================================
// K3b: reduce splits + bias — scalar per-thread outputs for 4x block count.
// out[r][h] = bias[h] + sum_s partial[s][r][h]
// 65536 threads (256 blocks x 256), 1 float each, MLP=8 scalar loads.
// Deterministic (fixed summation order).
// ============================================================================
__global__ void __launch_bounds__(256) outproj_reduce_kernel(
    const float* __restrict__ bias, float* __restrict__ out)
{
    int idx = blockIdx.x * 256 + threadIdx.x;     // 0 .. 65535 (512*128)
    int h = idx & (H_ - 1);
    float a = bias[h];
    #pragma unroll
    for (int s = 0; s < NSPLIT; ++s)
        a += g_PART[s*(B_*LQ_*H_) + idx];
    out[idx] = a;
}

// ============================================================================
extern "C" void kernel_launch(void* const* d_in, const int* in_sizes, int n_in,
                              void* d_out, int out_size)
{
    const float* queries    = (const float*)d_in[0];
    const float* keys       = (const float*)d_in[1];
    const float* values     = (const float*)d_in[2];
    const int*   valid_lens = (const int*)  d_in[3];
    const float* Wq         = (const float*)d_in[4];
    const float* Wk         = (const float*)d_in[5];
    const float* wv         = (const float*)d_in[6];
    const float* Wo_w       = (const float*)d_in[7];
    const float* Wo_b       = (const float*)d_in[8];
    float* out = (float*)d_out;

    proj_kernel<<<dim3(4, 2, 64), 256>>>(queries, keys, Wq, Wk);
    score_av_kernel<<<dim3(LQ_/8, NH_, B_), 256>>>(wv, valid_lens, values);
    outproj_split_kernel<<<dim3(8, 4, NSPLIT), 256>>>(Wo_w);
    outproj_reduce_kernel<<<dim3(B_*LQ_*H_/256), 256>>>(Wo_b, out);
}

// round 15
// speedup vs baseline: 1.2126x; 1.0284x over previous
#include <cuda_runtime.h>
#include <cuda_fp16.h>

#define B_   4
#define LQ_  128
#define LK_  256
#define D_   128
#define H_   128
#define NH_  8

#define L2E 1.4426950408889634f  // log2(e) for softmax exp

#define NSPLIT 8                 // K-splits for the output projection

// ---- scratch (static device memory; no allocation) ----
__device__ __align__(16) float  g_QH[B_*NH_*H_*LQ_];      // [b][n][h][q] fp32
__device__ __align__(16) __half g_KHh[B_*NH_*H_*LK_];     // [b][n][h][k] fp16
__device__ __align__(16) float  g_CONCAT[B_*LQ_*NH_*D_];  // [b][q][n*D+d]
__device__ __align__(16) float  g_PART[NSPLIT*B_*LQ_*H_]; // split-K partials

// ============================================================================
// K1: merged Q+K per-head projections — double-buffered smem. (round-13 exact)
// 64x64 tile, BK=16, 256 threads, 4x4 per thread; ONE barrier per BK chunk.
// grid = (4, 2, 64); z<32 -> K-proj (fp16 out), z>=32 -> Q-proj (fp32 out).
// ============================================================================
__global__ void __launch_bounds__(256) proj_kernel(
    const float* __restrict__ Q, const float* __restrict__ K,
    const float* __restrict__ Wq, const float* __restrict__ Wk)
{
    int zz = blockIdx.z;
    bool isq = zz >= 32;
    int bn = isq ? (zz - 32) : zz;
    int b = bn >> 3, n = bn & 7;
    int L = isq ? LQ_ : LK_;
    int l0 = blockIdx.x * 64;
    if (l0 >= L) return;                        // uniform per block
    const float* X = isq ? Q : K;
    const float* W = isq ? Wq : Wk;

    __shared__ float Ws[2][16][64];   // [buf][d][h]  8KB x2
    __shared__ float Xs[2][16][64];   // [buf][d][l]  8KB x2
    int h0 = blockIdx.y * 64;
    int tid = threadIdx.x;                 // 256
    int ty = tid >> 4, tx = tid & 15;      // 16x16
    float acc[4][4] = {};
    const float* Wp = W + (n*H_ + h0)*D_;
    const float* Xp = X + (b*L  + l0)*D_;
    int row = tid >> 2;          // 0..63
    int dq  = (tid & 3) * 4;     // 0,4,8,12

    float4 w4 = *(const float4*)(Wp + row*D_ + dq);
    float4 x4 = *(const float4*)(Xp + row*D_ + dq);
    #pragma unroll
    for (int c = 0; c < 8; ++c) {
        int buf = c & 1;
        Ws[buf][dq+0][row] = w4.x; Ws[buf][dq+1][row] = w4.y;
        Ws[buf][dq+2][row] = w4.z; Ws[buf][dq+3][row] = w4.w;
        Xs[buf][dq+0][row] = x4.x; Xs[buf][dq+1][row] = x4.y;
        Xs[buf][dq+2][row] = x4.z; Xs[buf][dq+3][row] = x4.w;
        if (c < 7) {
            w4 = *(const float4*)(Wp + row*D_ + (c+1)*16 + dq);
            x4 = *(const float4*)(Xp + row*D_ + (c+1)*16 + dq);
        }
        __syncthreads();
        #pragma unroll
        for (int dd = 0; dd < 16; ++dd) {
            float4 a4 = *(const float4*)&Ws[buf][dd][ty*4];
            float4 b4 = *(const float4*)&Xs[buf][dd][tx*4];
            float av[4] = {a4.x, a4.y, a4.z, a4.w};
            float bv[4] = {b4.x, b4.y, b4.z, b4.w};
            #pragma unroll
            for (int i = 0; i < 4; ++i)
                #pragma unroll
                for (int j = 0; j < 4; ++j)
                    acc[i][j] = fmaf(av[i], bv[j], acc[i][j]);
        }
    }
    if (isq) {
        float* Op = g_QH + ((b*NH_ + n)*H_ + h0 + ty*4)*L + l0 + tx*4;
        #pragma unroll
        for (int i = 0; i < 4; ++i)
            *(float4*)(Op + i*L) = make_float4(acc[i][0], acc[i][1], acc[i][2], acc[i][3]);
    } else {
        __half* Op = g_KHh + ((b*NH_ + n)*H_ + h0 + ty*4)*LK_ + l0 + tx*4;
        #pragma unroll
        for (int i = 0; i < 4; ++i) {
            __half2 h01 = __floats2half2_rn(acc[i][0], acc[i][1]);
            __half2 h23 = __floats2half2_rn(acc[i][2], acc[i][3]);
            *(__half2*)(Op + i*LK_)     = h01;
            *(__half2*)(Op + i*LK_ + 2) = h23;
        }
    }
}

// ============================================================================
// K2: FUSED scores + masked softmax + attn@V.
// Round-9/13 structure; ONLY change vs round-13: Qs staged as pre-duplicated
// half2 (cvt.rn.f16x2.f32 at staging — bit-identical to per-use cvt),
// removing one instruction per (dd,i) from the hot loop.
// ============================================================================
__global__ void __launch_bounds__(256) score_av_kernel(
    const float* __restrict__ wv, const int* __restrict__ valid_lens,
    const float* __restrict__ V)
{
    __shared__ __half Ks[16][LK_];     // [h][k] fp16  8KB
    __shared__ unsigned Qs2[16][8];    // [h][q] duplicated half2 (qh,qh)
    __shared__ float Wvs[16];
    __shared__ float redA[2][4][4];
    __shared__ float redB[2][4][4];
    __shared__ float attn_s[8][LK_];   // [q][k]   8KB
    __shared__ float Vs[32][D_];       // [k][d]  16KB

    int b = blockIdx.z, n = blockIdx.y;
    int q0 = blockIdx.x * 8;
    int tid = threadIdx.x;
    int qg = tid >> 7;      // 0..1
    int kg = tid & 127;     // 0..127
    int ks = kg * 2;
    int valid = valid_lens[b];
    bool active = ks < valid;
    const __half* KHp = g_KHh + ((b*NH_ + n)*H_)*LK_;
    const float*  QHp = g_QH  + ((b*NH_ + n)*H_)*LQ_ + q0;
    const float*  wvp = wv + n*H_;

    float acc[4][2] = {};

    for (int h0 = 0; h0 < H_; h0 += 16) {
        __syncthreads();
        #pragma unroll
        for (int t = 0; t < 2; ++t) {               // stage K chunk [16h][256k] fp16
            int idx = tid + t*256;                  // 512 uint4 (8 halves each)
            int r = idx >> 5, c = idx & 31;
            *(uint4*)&Ks[r][c*8] = *(const uint4*)(KHp + (h0+r)*LK_ + c*8);
        }
        if (tid < 128) {
            float qv = QHp[(h0 + (tid >> 3))*LQ_ + (tid & 7)];
            unsigned qh;
            asm("cvt.rn.f16x2.f32 %0, %1, %2;" : "=r"(qh) : "f"(qv), "f"(qv));
            Qs2[tid >> 3][tid & 7] = qh;
        }
        if (tid < 16) Wvs[tid] = wvp[h0 + tid];
        __syncthreads();

        if (active) {
            #pragma unroll
            for (int dd = 0; dd < 16; ++dd) {
                unsigned k2u = *(const unsigned*)&Ks[dd][ks];
                uint4 qh4 = *(const uint4*)&Qs2[dd][qg*4];
                float w = Wvs[dd];
                unsigned bqs[4] = {qh4.x, qh4.y, qh4.z, qh4.w};
                #pragma unroll
                for (int i = 0; i < 4; ++i) {
                    unsigned su, tu;
                    asm("add.rn.f16x2 %0, %1, %2;"  : "=r"(su) : "r"(bqs[i]), "r"(k2u));
                    asm("tanh.approx.f16x2 %0, %1;" : "=r"(tu) : "r"(su));
                    __half2 th = *reinterpret_cast<__half2*>(&tu);
                    float2 f = __half22float2(th);
                    acc[i][0] = fmaf(w, f.x, acc[i][0]);
                    acc[i][1] = fmaf(w, f.y, acc[i][1]);
                }
            }
        }
    }

    // ---- softmax over k (4 warps per q-group) ----
    float m[4];
    #pragma unroll
    for (int i = 0; i < 4; ++i) {
        float mm = -1e30f;
        #pragma unroll
        for (int j = 0; j < 2; ++j)
            if (ks + j < valid) mm = fmaxf(mm, acc[i][j]);
        m[i] = mm;
    }
    #pragma unroll
    for (int off = 16; off; off >>= 1)
        #pragma unroll
        for (int i = 0; i < 4; ++i)
            m[i] = fmaxf(m[i], __shfl_xor_sync(0xffffffffu, m[i], off));
    int w4 = (tid >> 5) & 3;
    if ((tid & 31) == 0)
        #pragma unroll
        for (int i = 0; i < 4; ++i) redA[qg][w4][i] = m[i];
    __syncthreads();
    #pragma unroll
    for (int i = 0; i < 4; ++i)
        m[i] = fmaxf(fmaxf(redA[qg][0][i], redA[qg][1][i]),
                     fmaxf(redA[qg][2][i], redA[qg][3][i]));

    float p[4][2], s[4] = {0.f, 0.f, 0.f, 0.f};
    #pragma unroll
    for (int i = 0; i < 4; ++i)
        #pragma unroll
        for (int j = 0; j < 2; ++j) {
            float e;
            asm("ex2.approx.f32 %0, %1;" : "=f"(e) : "f"((acc[i][j] - m[i]) * L2E));
            bool v = (ks + j) < valid;
            p[i][j] = v ? e : 0.0f;
            s[i] += p[i][j];
        }
    #pragma unroll
    for (int off = 16; off; off >>= 1)
        #pragma unroll
        for (int i = 0; i < 4; ++i)
            s[i] += __shfl_xor_sync(0xffffffffu, s[i], off);
    if ((tid & 31) == 0)
        #pragma unroll
        for (int i = 0; i < 4; ++i) redB[qg][w4][i] = s[i];
    __syncthreads();

    #pragma unroll
    for (int i = 0; i < 4; ++i) {
        float inv = 1.0f / (redB[qg][0][i] + redB[qg][1][i] +
                            redB[qg][2][i] + redB[qg][3][i]);
        *(float2*)&attn_s[qg*4+i][ks] = make_float2(p[i][0]*inv, p[i][1]*inv);
    }
    // (attn_s fully written for k in [0,256): zeros beyond valid)

    // ---- Phase 2: out = attn_s @ V[b], thread = 1q x 4d ----
    int ty = tid >> 5;          // q row 0..7
    int tx = tid & 31;          // d group of 4
    float oa[4] = {};
    int kend = (valid + 31) & ~31;
    const float* Vp = V + (b*LK_)*D_;
    for (int k0 = 0; k0 < kend; k0 += 32) {
        __syncthreads();        // also orders attn_s writes on first iter
        #pragma unroll
        for (int t = 0; t < 4; ++t) {   // stage V chunk [32k][128d]
            int idx = tid + t*256;
            int r = idx >> 5, c4 = idx & 31;
            *(float4*)&Vs[r][c4*4] = *(const float4*)(Vp + (k0+r)*D_ + c4*4);
        }
        __syncthreads();
        #pragma unroll
        for (int kk = 0; kk < 32; ++kk) {
            float a = attn_s[ty][k0+kk];          // broadcast within warp
            float4 v4 = *(const float4*)&Vs[kk][tx*4];
            oa[0] = fmaf(a, v4.x, oa[0]);
            oa[1] = fmaf(a, v4.y, oa[1]);
            oa[2] = fmaf(a, v4.z, oa[2]);
            oa[3] = fmaf(a, v4.w, oa[3]);
        }
    }
    float* Cp = g_CONCAT + (b*LQ_ + q0 + ty)*(NH_*D_) + n*D_ + tx*4;
    *(float4*)Cp = make_float4(oa[0], oa[1], oa[2], oa[3]);
}

// ============================================================================
// K3a: split-K output projection partials — double-buffered (proj pattern).
// grid (8 row-tiles, 4 h-tiles, 8 splits), 256 threads.
// Tile: 64 rows x 32 h, K-chunk = 128 per split, BK=16 -> 8 iters, 1 barrier each.
// Bs rows 144B (16B multiple) for aligned float4 reads.
// ============================================================================
__global__ void __launch_bounds__(256) outproj_split_kernel(
    const float* __restrict__ Wo)
{
    __shared__ float As[2][16][65];   // [buf][j][row] (scalar-read only)
    __shared__ float Bs[2][16][36];   // [buf][j][h]   (float4-read, aligned rows)
    int r0 = blockIdx.x * 64;
    int h0 = blockIdx.y * 32;
    int split = blockIdx.z;
    int j0base = split * (NH_*D_ / NSPLIT);   // 128-wide K chunk
    int tid = threadIdx.x;          // 256
    int ry = tid >> 3;              // 0..31 -> row pair
    int tx = tid & 7;               // -> h group of 4
    const float* Cc = g_CONCAT;
    float acc[2][4] = {};

    int arow = tid >> 2;            // 0..63 (A staging row)
    int ajq  = (tid & 3) * 4;       // j offset 0,4,8,12
    int bhr  = (tid & 127) >> 2;    // 0..31 (B staging h), threads 0..127 only
    int bjq  = (tid & 3) * 4;

    float4 a4 = *(const float4*)(Cc + (r0+arow)*(NH_*D_) + j0base + ajq);
    float4 w4;
    if (tid < 128) w4 = *(const float4*)(Wo + (h0+bhr)*(NH_*D_) + j0base + bjq);

    #pragma unroll
    for (int jc = 0; jc < 8; ++jc) {
        int buf = jc & 1;
        As[buf][ajq+0][arow] = a4.x; As[buf][ajq+1][arow] = a4.y;
        As[buf][ajq+2][arow] = a4.z; As[buf][ajq+3][arow] = a4.w;
        if (tid < 128) {
            Bs[buf][bjq+0][bhr] = w4.x; Bs[buf][bjq+1][bhr] = w4.y;
            Bs[buf][bjq+2][bhr] = w4.z; Bs[buf][bjq+3][bhr] = w4.w;
        }
        if (jc < 7) {
            int j0n = j0base + (jc+1) * 16;
            a4 = *(const float4*)(Cc + (r0+arow)*(NH_*D_) + j0n + ajq);
            if (tid < 128) w4 = *(const float4*)(Wo + (h0+bhr)*(NH_*D_) + j0n + bjq);
        }
        __syncthreads();
        #pragma unroll
        for (int jj = 0; jj < 16; ++jj) {
            float a0 = As[buf][jj][ry*2+0];
            float a1 = As[buf][jj][ry*2+1];
            float4 b4 = *(const float4*)&Bs[buf][jj][tx*4];
            float bv[4] = {b4.x, b4.y, b4.z, b4.w};
            #pragma unroll
            for (int j = 0; j < 4; ++j) {
                acc[0][j] = fmaf(a0, bv[j], acc[0][j]);
                acc[1][j] = fmaf(a1, bv[j], acc[1][j]);
            }
        }
    }
    float* Pp = g_PART + ((split*(B_*LQ_)) + r0 + ry*2)*H_ + h0 + tx*4;
    #pragma unroll
    for (int i = 0; i < 2; ++i)
        *(float4*)(Pp + i*H_) = make_float4(acc[i][0], acc[i][1], acc[i][2], acc[i][3]);
}

// ============================================================================
// K3b: reduce splits + bias.  (round-13 exact)
// out[r][h] = bias[h] + sum_s partial[s][r][h]; 65536 threads, scalar each.
// ============================================================================
__global__ void __launch_bounds__(256) outproj_reduce_kernel(
    const float* __restrict__ bias, float* __restrict__ out)
{
    int idx = blockIdx.x * 256 + threadIdx.x;     // 0 .. 65535 (512*128)
    int h = idx & (H_ - 1);
    float a = bias[h];
    #pragma unroll
    for (int s = 0; s < NSPLIT; ++s)
        a += g_PART[s*(B_*LQ_*H_) + idx];
    out[idx] = a;
}

// ============================================================================
extern "C" void kernel_launch(void* const* d_in, const int* in_sizes, int n_in,
                              void* d_out, int out_size)
{
    const float* queries    = (const float*)d_in[0];
    const float* keys       = (const float*)d_in[1];
    const float* values     = (const float*)d_in[2];
    const int*   valid_lens = (const int*)  d_in[3];
    const float* Wq         = (const float*)d_in[4];
    const float* Wk         = (const float*)d_in[5];
    const float* wv         = (const float*)d_in[6];
    const float* Wo_w       = (const float*)d_in[7];
    const float* Wo_b       = (const float*)d_in[8];
    float* out = (float*)d_out;

    proj_kernel<<<dim3(4, 2, 64), 256>>>(queries, keys, Wq, Wk);
    score_av_kernel<<<dim3(LQ_/8, NH_, B_), 256>>>(wv, valid_lens, values);
    outproj_split_kernel<<<dim3(8, 4, NSPLIT), 256>>>(Wo_w);
    outproj_reduce_kernel<<<dim3(B_*LQ_*H_/256), 256>>>(Wo_b, out);
}

// round 16
// speedup vs baseline: 1.3072x; 1.0780x over previous
#include <cuda_runtime.h>
#include <cuda_fp16.h>

#define B_   4
#define LQ_  128
#define LK_  256
#define D_   128
#define H_   128
#define NH_  8

#define L2E 1.4426950408889634f  // log2(e) for softmax exp

#define NSPLIT 8                 // K-splits for the output projection

// ---- scratch (static device memory; no allocation) ----
__device__ __align__(16) float  g_QH[B_*NH_*H_*LQ_];      // [b][n][h][q] fp32
__device__ __align__(16) __half g_KHh[B_*NH_*H_*LK_];     // [b][n][h][k] fp16
__device__ __align__(16) float  g_CONCAT[B_*LQ_*NH_*D_];  // [b][q][n*D+d]
__device__ __align__(16) float  g_PART[NSPLIT*B_*LQ_*H_]; // split-K partials

// ============================================================================
// K1: merged Q+K per-head projections — double-buffered smem. (unchanged)
// 64x64 tile, BK=16, 256 threads, 4x4 per thread; ONE barrier per BK chunk.
// grid = (4, 2, 64); z<32 -> K-proj (fp16 out), z>=32 -> Q-proj (fp32 out).
// ============================================================================
__global__ void __launch_bounds__(256) proj_kernel(
    const float* __restrict__ Q, const float* __restrict__ K,
    const float* __restrict__ Wq, const float* __restrict__ Wk)
{
    int zz = blockIdx.z;
    bool isq = zz >= 32;
    int bn = isq ? (zz - 32) : zz;
    int b = bn >> 3, n = bn & 7;
    int L = isq ? LQ_ : LK_;
    int l0 = blockIdx.x * 64;
    if (l0 >= L) return;                        // uniform per block
    const float* X = isq ? Q : K;
    const float* W = isq ? Wq : Wk;

    __shared__ float Ws[2][16][64];   // [buf][d][h]
    __shared__ float Xs[2][16][64];   // [buf][d][l]
    int h0 = blockIdx.y * 64;
    int tid = threadIdx.x;                 // 256
    int ty = tid >> 4, tx = tid & 15;      // 16x16
    float acc[4][4] = {};
    const float* Wp = W + (n*H_ + h0)*D_;
    const float* Xp = X + (b*L  + l0)*D_;
    int row = tid >> 2;          // 0..63
    int dq  = (tid & 3) * 4;     // 0,4,8,12

    float4 w4 = *(const float4*)(Wp + row*D_ + dq);
    float4 x4 = *(const float4*)(Xp + row*D_ + dq);
    #pragma unroll
    for (int c = 0; c < 8; ++c) {
        int buf = c & 1;
        Ws[buf][dq+0][row] = w4.x; Ws[buf][dq+1][row] = w4.y;
        Ws[buf][dq+2][row] = w4.z; Ws[buf][dq+3][row] = w4.w;
        Xs[buf][dq+0][row] = x4.x; Xs[buf][dq+1][row] = x4.y;
        Xs[buf][dq+2][row] = x4.z; Xs[buf][dq+3][row] = x4.w;
        if (c < 7) {
            w4 = *(const float4*)(Wp + row*D_ + (c+1)*16 + dq);
            x4 = *(const float4*)(Xp + row*D_ + (c+1)*16 + dq);
        }
        __syncthreads();
        #pragma unroll
        for (int dd = 0; dd < 16; ++dd) {
            float4 a4 = *(const float4*)&Ws[buf][dd][ty*4];
            float4 b4 = *(const float4*)&Xs[buf][dd][tx*4];
            float av[4] = {a4.x, a4.y, a4.z, a4.w};
            float bv[4] = {b4.x, b4.y, b4.z, b4.w};
            #pragma unroll
            for (int i = 0; i < 4; ++i)
                #pragma unroll
                for (int j = 0; j < 4; ++j)
                    acc[i][j] = fmaf(av[i], bv[j], acc[i][j]);
        }
    }
    if (isq) {
        float* Op = g_QH + ((b*NH_ + n)*H_ + h0 + ty*4)*L + l0 + tx*4;
        #pragma unroll
        for (int i = 0; i < 4; ++i)
            *(float4*)(Op + i*L) = make_float4(acc[i][0], acc[i][1], acc[i][2], acc[i][3]);
    } else {
        __half* Op = g_KHh + ((b*NH_ + n)*H_ + h0 + ty*4)*LK_ + l0 + tx*4;
        #pragma unroll
        for (int i = 0; i < 4; ++i) {
            __half2 h01 = __floats2half2_rn(acc[i][0], acc[i][1]);
            __half2 h23 = __floats2half2_rn(acc[i][2], acc[i][3]);
            *(__half2*)(Op + i*LK_)     = h01;
            *(__half2*)(Op + i*LK_ + 2) = h23;
        }
    }
}

// ============================================================================
// K2: FUSED scores + masked softmax + attn@V — NOW double-buffered both phases.
// Phase 1: Ks/Qs2/Wvs ping-pong, register prefetch, 1 barrier per 16h chunk.
// Phase 2: Vs [2][16][D] ping-pong, register prefetch, 1 barrier per 16k chunk.
// Arithmetic and ordering byte-identical to the 77.8us version.
// ============================================================================
__global__ void __launch_bounds__(256) score_av_kernel(
    const float* __restrict__ wv, const int* __restrict__ valid_lens,
    const float* __restrict__ V)
{
    __shared__ __half Ks[2][16][LK_];  // [buf][h][k] fp16  16KB
    __shared__ unsigned Qs2[2][16][8]; // [buf][h][q] dup half2  1KB
    __shared__ float Wvs[2][16];
    __shared__ float redA[2][4][4];
    __shared__ float redB[2][4][4];
    __shared__ float attn_s[8][LK_];   // [q][k]   8KB
    __shared__ float Vs[2][16][D_];    // [buf][k][d]  16KB

    int b = blockIdx.z, n = blockIdx.y;
    int q0 = blockIdx.x * 8;
    int tid = threadIdx.x;
    int qg = tid >> 7;      // 0..1
    int kg = tid & 127;     // 0..127
    int ks = kg * 2;
    int valid = valid_lens[b];
    bool active = ks < valid;
    const __half* KHp = g_KHh + ((b*NH_ + n)*H_)*LK_;
    const float*  QHp = g_QH  + ((b*NH_ + n)*H_)*LQ_ + q0;
    const float*  wvp = wv + n*H_;

    float acc[4][2] = {};

    // ---- Phase 1: scores, Ks double-buffered ----
    int srow = tid >> 5;              // 0..7 (stages rows srow, srow+8)
    int scol = (tid & 31) * 8;        // halves, 16B aligned
    uint4 ra = *(const uint4*)(KHp + srow*LK_ + scol);
    uint4 rb = *(const uint4*)(KHp + (srow+8)*LK_ + scol);
    float qpre = 0.f;
    if (tid < 128) qpre = QHp[(tid >> 3)*LQ_ + (tid & 7)];
    float wpre = (tid < 16) ? wvp[tid] : 0.f;

    #pragma unroll
    for (int c = 0; c < 8; ++c) {
        int buf = c & 1;
        *(uint4*)&Ks[buf][srow][scol]   = ra;
        *(uint4*)&Ks[buf][srow+8][scol] = rb;
        if (tid < 128) {
            unsigned qh;
            asm("cvt.rn.f16x2.f32 %0, %1, %2;" : "=r"(qh) : "f"(qpre), "f"(qpre));
            Qs2[buf][tid >> 3][tid & 7] = qh;
        }
        if (tid < 16) Wvs[buf][tid] = wpre;
        if (c < 7) {
            const __half* src = KHp + (c+1)*16*LK_;
            ra = *(const uint4*)(src + srow*LK_ + scol);
            rb = *(const uint4*)(src + (srow+8)*LK_ + scol);
            if (tid < 128) qpre = QHp[((c+1)*16 + (tid >> 3))*LQ_ + (tid & 7)];
            if (tid < 16)  wpre = wvp[(c+1)*16 + tid];
        }
        __syncthreads();
        if (active) {
            #pragma unroll
            for (int dd = 0; dd < 16; ++dd) {
                unsigned k2u = *(const unsigned*)&Ks[buf][dd][ks];
                uint4 qh4 = *(const uint4*)&Qs2[buf][dd][qg*4];
                float w = Wvs[buf][dd];
                unsigned bqs[4] = {qh4.x, qh4.y, qh4.z, qh4.w};
                #pragma unroll
                for (int i = 0; i < 4; ++i) {
                    unsigned su, tu;
                    asm("add.rn.f16x2 %0, %1, %2;"  : "=r"(su) : "r"(bqs[i]), "r"(k2u));
                    asm("tanh.approx.f16x2 %0, %1;" : "=r"(tu) : "r"(su));
                    __half2 th = *reinterpret_cast<__half2*>(&tu);
                    float2 f = __half22float2(th);
                    acc[i][0] = fmaf(w, f.x, acc[i][0]);
                    acc[i][1] = fmaf(w, f.y, acc[i][1]);
                }
            }
        }
    }

    // ---- softmax over k (4 warps per q-group) — unchanged ----
    float m[4];
    #pragma unroll
    for (int i = 0; i < 4; ++i) {
        float mm = -1e30f;
        #pragma unroll
        for (int j = 0; j < 2; ++j)
            if (ks + j < valid) mm = fmaxf(mm, acc[i][j]);
        m[i] = mm;
    }
    #pragma unroll
    for (int off = 16; off; off >>= 1)
        #pragma unroll
        for (int i = 0; i < 4; ++i)
            m[i] = fmaxf(m[i], __shfl_xor_sync(0xffffffffu, m[i], off));
    int w4 = (tid >> 5) & 3;
    if ((tid & 31) == 0)
        #pragma unroll
        for (int i = 0; i < 4; ++i) redA[qg][w4][i] = m[i];
    __syncthreads();
    #pragma unroll
    for (int i = 0; i < 4; ++i)
        m[i] = fmaxf(fmaxf(redA[qg][0][i], redA[qg][1][i]),
                     fmaxf(redA[qg][2][i], redA[qg][3][i]));

    float p[4][2], s[4] = {0.f, 0.f, 0.f, 0.f};
    #pragma unroll
    for (int i = 0; i < 4; ++i)
        #pragma unroll
        for (int j = 0; j < 2; ++j) {
            float e;
            asm("ex2.approx.f32 %0, %1;" : "=f"(e) : "f"((acc[i][j] - m[i]) * L2E));
            bool v = (ks + j) < valid;
            p[i][j] = v ? e : 0.0f;
            s[i] += p[i][j];
        }
    #pragma unroll
    for (int off = 16; off; off >>= 1)
        #pragma unroll
        for (int i = 0; i < 4; ++i)
            s[i] += __shfl_xor_sync(0xffffffffu, s[i], off);
    if ((tid & 31) == 0)
        #pragma unroll
        for (int i = 0; i < 4; ++i) redB[qg][w4][i] = s[i];
    __syncthreads();

    #pragma unroll
    for (int i = 0; i < 4; ++i) {
        float inv = 1.0f / (redB[qg][0][i] + redB[qg][1][i] +
                            redB[qg][2][i] + redB[qg][3][i]);
        *(float2*)&attn_s[qg*4+i][ks] = make_float2(p[i][0]*inv, p[i][1]*inv);
    }
    // (attn_s fully written for k in [0,256): zeros beyond valid)

    // ---- Phase 2: out = attn_s @ V[b], Vs double-buffered 16-row chunks ----
    int ty = tid >> 5;          // q row 0..7
    int tx = tid & 31;          // d group of 4
    float oa[4] = {};
    int nch = (valid + 15) >> 4;          // 16-row chunks
    const float* Vp = V + (b*LK_)*D_;
    int vrow = tid >> 5;                  // 0..7 (stages rows vrow, vrow+8)
    int vcol = (tid & 31) * 4;

    float4 va = *(const float4*)(Vp + vrow*D_ + vcol);
    float4 vb = *(const float4*)(Vp + (vrow+8)*D_ + vcol);
    for (int c = 0; c < nch; ++c) {
        int buf = c & 1;
        *(float4*)&Vs[buf][vrow][vcol]   = va;
        *(float4*)&Vs[buf][vrow+8][vcol] = vb;
        if (c + 1 < 16) {                 // V always has 256 rows: safe prefetch
            const float* src = Vp + (c+1)*16*D_;
            va = *(const float4*)(src + vrow*D_ + vcol);
            vb = *(const float4*)(src + (vrow+8)*D_ + vcol);
        }
        __syncthreads();                  // first iter also orders attn_s writes
        int k0 = c * 16;
        #pragma unroll
        for (int kk = 0; kk < 16; ++kk) {
            float a = attn_s[ty][k0+kk];  // broadcast within warp
            float4 v4 = *(const float4*)&Vs[buf][kk][tx*4];
            oa[0] = fmaf(a, v4.x, oa[0]);
            oa[1] = fmaf(a, v4.y, oa[1]);
            oa[2] = fmaf(a, v4.z, oa[2]);
            oa[3] = fmaf(a, v4.w, oa[3]);
        }
    }
    float* Cp = g_CONCAT + (b*LQ_ + q0 + ty)*(NH_*D_) + n*D_ + tx*4;
    *(float4*)Cp = make_float4(oa[0], oa[1], oa[2], oa[3]);
}

// ============================================================================
// K3a: split-K output projection partials — double-buffered. (unchanged)
// grid (8 row-tiles, 4 h-tiles, 8 splits), 256 threads.
// ============================================================================
__global__ void __launch_bounds__(256) outproj_split_kernel(
    const float* __restrict__ Wo)
{
    __shared__ float As[2][16][65];   // [buf][j][row] (scalar-read only)
    __shared__ float Bs[2][16][36];   // [buf][j][h]   (float4-read, aligned rows)
    int r0 = blockIdx.x * 64;
    int h0 = blockIdx.y * 32;
    int split = blockIdx.z;
    int j0base = split * (NH_*D_ / NSPLIT);   // 128-wide K chunk
    int tid = threadIdx.x;          // 256
    int ry = tid >> 3;              // 0..31 -> row pair
    int tx = tid & 7;               // -> h group of 4
    const float* Cc = g_CONCAT;
    float acc[2][4] = {};

    int arow = tid >> 2;            // 0..63 (A staging row)
    int ajq  = (tid & 3) * 4;       // j offset 0,4,8,12
    int bhr  = (tid & 127) >> 2;    // 0..31 (B staging h), threads 0..127 only
    int bjq  = (tid & 3) * 4;

    float4 a4 = *(const float4*)(Cc + (r0+arow)*(NH_*D_) + j0base + ajq);
    float4 w4;
    if (tid < 128) w4 = *(const float4*)(Wo + (h0+bhr)*(NH_*D_) + j0base + bjq);

    #pragma unroll
    for (int jc = 0; jc < 8; ++jc) {
        int buf = jc & 1;
        As[buf][ajq+0][arow] = a4.x; As[buf][ajq+1][arow] = a4.y;
        As[buf][ajq+2][arow] = a4.z; As[buf][ajq+3][arow] = a4.w;
        if (tid < 128) {
            Bs[buf][bjq+0][bhr] = w4.x; Bs[buf][bjq+1][bhr] = w4.y;
            Bs[buf][bjq+2][bhr] = w4.z; Bs[buf][bjq+3][bhr] = w4.w;
        }
        if (jc < 7) {
            int j0n = j0base + (jc+1) * 16;
            a4 = *(const float4*)(Cc + (r0+arow)*(NH_*D_) + j0n + ajq);
            if (tid < 128) w4 = *(const float4*)(Wo + (h0+bhr)*(NH_*D_) + j0n + bjq);
        }
        __syncthreads();
        #pragma unroll
        for (int jj = 0; jj < 16; ++jj) {
            float a0 = As[buf][jj][ry*2+0];
            float a1 = As[buf][jj][ry*2+1];
            float4 b4 = *(const float4*)&Bs[buf][jj][tx*4];
            float bv[4] = {b4.x, b4.y, b4.z, b4.w};
            #pragma unroll
            for (int j = 0; j < 4; ++j) {
                acc[0][j] = fmaf(a0, bv[j], acc[0][j]);
                acc[1][j] = fmaf(a1, bv[j], acc[1][j]);
            }
        }
    }
    float* Pp = g_PART + ((split*(B_*LQ_)) + r0 + ry*2)*H_ + h0 + tx*4;
    #pragma unroll
    for (int i = 0; i < 2; ++i)
        *(float4*)(Pp + i*H_) = make_float4(acc[i][0], acc[i][1], acc[i][2], acc[i][3]);
}

// ============================================================================
// K3b: reduce splits + bias.  (unchanged)
// out[r][h] = bias[h] + sum_s partial[s][r][h]; 65536 threads, scalar each.
// ============================================================================
__global__ void __launch_bounds__(256) outproj_reduce_kernel(
    const float* __restrict__ bias, float* __restrict__ out)
{
    int idx = blockIdx.x * 256 + threadIdx.x;     // 0 .. 65535 (512*128)
    int h = idx & (H_ - 1);
    float a = bias[h];
    #pragma unroll
    for (int s = 0; s < NSPLIT; ++s)
        a += g_PART[s*(B_*LQ_*H_) + idx];
    out[idx] = a;
}

// ============================================================================
extern "C" void kernel_launch(void* const* d_in, const int* in_sizes, int n_in,
                              void* d_out, int out_size)
{
    const float* queries    = (const float*)d_in[0];
    const float* keys       = (const float*)d_in[1];
    const float* values     = (const float*)d_in[2];
    const int*   valid_lens = (const int*)  d_in[3];
    const float* Wq         = (const float*)d_in[4];
    const float* Wk         = (const float*)d_in[5];
    const float* wv         = (const float*)d_in[6];
    const float* Wo_w       = (const float*)d_in[7];
    const float* Wo_b       = (const float*)d_in[8];
    float* out = (float*)d_out;

    proj_kernel<<<dim3(4, 2, 64), 256>>>(queries, keys, Wq, Wk);
    score_av_kernel<<<dim3(LQ_/8, NH_, B_), 256>>>(wv, valid_lens, values);
    outproj_split_kernel<<<dim3(8, 4, NSPLIT), 256>>>(Wo_w);
    outproj_reduce_kernel<<<dim3(B_*LQ_*H_/256), 256>>>(Wo_b, out);
}

// round 17
// speedup vs baseline: 1.3368x; 1.0227x over previous
#include <cuda_runtime.h>
#include <cuda_fp16.h>

#define B_   4
#define LQ_  128
#define LK_  256
#define D_   128
#define H_   128
#define NH_  8

#define L2E 1.4426950408889634f  // log2(e) for softmax exp

#define NSPLIT 8                 // K-splits for the output projection

// ---- scratch (static device memory; no allocation) ----
__device__ __align__(16) float  g_QH[B_*NH_*H_*LQ_];      // [b][n][h][q] fp32
__device__ __align__(16) __half g_KHh[B_*NH_*H_*LK_];     // [b][n][h][k] fp16
__device__ __align__(16) float  g_CONCAT[B_*LQ_*NH_*D_];  // [b][q][n*D+d]
__device__ __align__(16) float  g_PART[NSPLIT*B_*LQ_*H_]; // split-K partials
__device__ int g_cnt[8][4];                               // last-block counters (zero-init)

// ============================================================================
// K1: merged Q+K per-head projections — double-buffered smem, compact grid.
// 64x64 tile, BK=16, 256 threads, 4x4 per thread; ONE barrier per BK chunk.
// grid = (4, 2, 48): z<32 -> K-proj (bn=z, l0=x*64);
//                    z>=32 -> Q-proj (bn=(z-32)*2+(x>>1), l0=(x&1)*64).
// Every block active (was 512 blocks with 128 no-ops).
// ============================================================================
__global__ void __launch_bounds__(256) proj_kernel(
    const float* __restrict__ Q, const float* __restrict__ K,
    const float* __restrict__ Wq, const float* __restrict__ Wk)
{
    int zz = blockIdx.z;
    bool isq = zz >= 32;
    int bn, l0, L;
    if (isq) {
        int zq = zz - 32;                       // 0..15
        bn = zq*2 + (blockIdx.x >> 1);          // 0..31
        l0 = (blockIdx.x & 1) * 64;             // 0,64
        L  = LQ_;
    } else {
        bn = zz;                                // 0..31
        l0 = blockIdx.x * 64;                   // 0..192
        L  = LK_;
    }
    int b = bn >> 3, n = bn & 7;
    const float* X = isq ? Q : K;
    const float* W = isq ? Wq : Wk;

    __shared__ float Ws[2][16][64];   // [buf][d][h]
    __shared__ float Xs[2][16][64];   // [buf][d][l]
    int h0 = blockIdx.y * 64;
    int tid = threadIdx.x;                 // 256
    int ty = tid >> 4, tx = tid & 15;      // 16x16
    float acc[4][4] = {};
    const float* Wp = W + (n*H_ + h0)*D_;
    const float* Xp = X + (b*L  + l0)*D_;
    int row = tid >> 2;          // 0..63
    int dq  = (tid & 3) * 4;     // 0,4,8,12

    float4 w4 = *(const float4*)(Wp + row*D_ + dq);
    float4 x4 = *(const float4*)(Xp + row*D_ + dq);
    #pragma unroll
    for (int c = 0; c < 8; ++c) {
        int buf = c & 1;
        Ws[buf][dq+0][row] = w4.x; Ws[buf][dq+1][row] = w4.y;
        Ws[buf][dq+2][row] = w4.z; Ws[buf][dq+3][row] = w4.w;
        Xs[buf][dq+0][row] = x4.x; Xs[buf][dq+1][row] = x4.y;
        Xs[buf][dq+2][row] = x4.z; Xs[buf][dq+3][row] = x4.w;
        if (c < 7) {
            w4 = *(const float4*)(Wp + row*D_ + (c+1)*16 + dq);
            x4 = *(const float4*)(Xp + row*D_ + (c+1)*16 + dq);
        }
        __syncthreads();
        #pragma unroll
        for (int dd = 0; dd < 16; ++dd) {
            float4 a4 = *(const float4*)&Ws[buf][dd][ty*4];
            float4 b4 = *(const float4*)&Xs[buf][dd][tx*4];
            float av[4] = {a4.x, a4.y, a4.z, a4.w};
            float bv[4] = {b4.x, b4.y, b4.z, b4.w};
            #pragma unroll
            for (int i = 0; i < 4; ++i)
                #pragma unroll
                for (int j = 0; j < 4; ++j)
                    acc[i][j] = fmaf(av[i], bv[j], acc[i][j]);
        }
    }
    if (isq) {
        float* Op = g_QH + ((b*NH_ + n)*H_ + h0 + ty*4)*L + l0 + tx*4;
        #pragma unroll
        for (int i = 0; i < 4; ++i)
            *(float4*)(Op + i*L) = make_float4(acc[i][0], acc[i][1], acc[i][2], acc[i][3]);
    } else {
        __half* Op = g_KHh + ((b*NH_ + n)*H_ + h0 + ty*4)*LK_ + l0 + tx*4;
        #pragma unroll
        for (int i = 0; i < 4; ++i) {
            __half2 h01 = __floats2half2_rn(acc[i][0], acc[i][1]);
            __half2 h23 = __floats2half2_rn(acc[i][2], acc[i][3]);
            *(__half2*)(Op + i*LK_)     = h01;
            *(__half2*)(Op + i*LK_ + 2) = h23;
        }
    }
}

// ============================================================================
// K2: FUSED scores + masked softmax + attn@V — double-buffered both phases.
// (byte-identical to the 72.2us version; locked)
// ============================================================================
__global__ void __launch_bounds__(256) score_av_kernel(
    const float* __restrict__ wv, const int* __restrict__ valid_lens,
    const float* __restrict__ V)
{
    __shared__ __half Ks[2][16][LK_];  // [buf][h][k] fp16  16KB
    __shared__ unsigned Qs2[2][16][8]; // [buf][h][q] dup half2  1KB
    __shared__ float Wvs[2][16];
    __shared__ float redA[2][4][4];
    __shared__ float redB[2][4][4];
    __shared__ float attn_s[8][LK_];   // [q][k]   8KB
    __shared__ float Vs[2][16][D_];    // [buf][k][d]  16KB

    int b = blockIdx.z, n = blockIdx.y;
    int q0 = blockIdx.x * 8;
    int tid = threadIdx.x;
    int qg = tid >> 7;      // 0..1
    int kg = tid & 127;     // 0..127
    int ks = kg * 2;
    int valid = valid_lens[b];
    bool active = ks < valid;
    const __half* KHp = g_KHh + ((b*NH_ + n)*H_)*LK_;
    const float*  QHp = g_QH  + ((b*NH_ + n)*H_)*LQ_ + q0;
    const float*  wvp = wv + n*H_;

    float acc[4][2] = {};

    // ---- Phase 1: scores, Ks double-buffered ----
    int srow = tid >> 5;              // 0..7 (stages rows srow, srow+8)
    int scol = (tid & 31) * 8;        // halves, 16B aligned
    uint4 ra = *(const uint4*)(KHp + srow*LK_ + scol);
    uint4 rb = *(const uint4*)(KHp + (srow+8)*LK_ + scol);
    float qpre = 0.f;
    if (tid < 128) qpre = QHp[(tid >> 3)*LQ_ + (tid & 7)];
    float wpre = (tid < 16) ? wvp[tid] : 0.f;

    #pragma unroll
    for (int c = 0; c < 8; ++c) {
        int buf = c & 1;
        *(uint4*)&Ks[buf][srow][scol]   = ra;
        *(uint4*)&Ks[buf][srow+8][scol] = rb;
        if (tid < 128) {
            unsigned qh;
            asm("cvt.rn.f16x2.f32 %0, %1, %2;" : "=r"(qh) : "f"(qpre), "f"(qpre));
            Qs2[buf][tid >> 3][tid & 7] = qh;
        }
        if (tid < 16) Wvs[buf][tid] = wpre;
        if (c < 7) {
            const __half* src = KHp + (c+1)*16*LK_;
            ra = *(const uint4*)(src + srow*LK_ + scol);
            rb = *(const uint4*)(src + (srow+8)*LK_ + scol);
            if (tid < 128) qpre = QHp[((c+1)*16 + (tid >> 3))*LQ_ + (tid & 7)];
            if (tid < 16)  wpre = wvp[(c+1)*16 + tid];
        }
        __syncthreads();
        if (active) {
            #pragma unroll
            for (int dd = 0; dd < 16; ++dd) {
                unsigned k2u = *(const unsigned*)&Ks[buf][dd][ks];
                uint4 qh4 = *(const uint4*)&Qs2[buf][dd][qg*4];
                float w = Wvs[buf][dd];
                unsigned bqs[4] = {qh4.x, qh4.y, qh4.z, qh4.w};
                #pragma unroll
                for (int i = 0; i < 4; ++i) {
                    unsigned su, tu;
                    asm("add.rn.f16x2 %0, %1, %2;"  : "=r"(su) : "r"(bqs[i]), "r"(k2u));
                    asm("tanh.approx.f16x2 %0, %1;" : "=r"(tu) : "r"(su));
                    __half2 th = *reinterpret_cast<__half2*>(&tu);
                    float2 f = __half22float2(th);
                    acc[i][0] = fmaf(w, f.x, acc[i][0]);
                    acc[i][1] = fmaf(w, f.y, acc[i][1]);
                }
            }
        }
    }

    // ---- softmax over k (4 warps per q-group) ----
    float m[4];
    #pragma unroll
    for (int i = 0; i < 4; ++i) {
        float mm = -1e30f;
        #pragma unroll
        for (int j = 0; j < 2; ++j)
            if (ks + j < valid) mm = fmaxf(mm, acc[i][j]);
        m[i] = mm;
    }
    #pragma unroll
    for (int off = 16; off; off >>= 1)
        #pragma unroll
        for (int i = 0; i < 4; ++i)
            m[i] = fmaxf(m[i], __shfl_xor_sync(0xffffffffu, m[i], off));
    int w4 = (tid >> 5) & 3;
    if ((tid & 31) == 0)
        #pragma unroll
        for (int i = 0; i < 4; ++i) redA[qg][w4][i] = m[i];
    __syncthreads();
    #pragma unroll
    for (int i = 0; i < 4; ++i)
        m[i] = fmaxf(fmaxf(redA[qg][0][i], redA[qg][1][i]),
                     fmaxf(redA[qg][2][i], redA[qg][3][i]));

    float p[4][2], s[4] = {0.f, 0.f, 0.f, 0.f};
    #pragma unroll
    for (int i = 0; i < 4; ++i)
        #pragma unroll
        for (int j = 0; j < 2; ++j) {
            float e;
            asm("ex2.approx.f32 %0, %1;" : "=f"(e) : "f"((acc[i][j] - m[i]) * L2E));
            bool v = (ks + j) < valid;
            p[i][j] = v ? e : 0.0f;
            s[i] += p[i][j];
        }
    #pragma unroll
    for (int off = 16; off; off >>= 1)
        #pragma unroll
        for (int i = 0; i < 4; ++i)
            s[i] += __shfl_xor_sync(0xffffffffu, s[i], off);
    if ((tid & 31) == 0)
        #pragma unroll
        for (int i = 0; i < 4; ++i) redB[qg][w4][i] = s[i];
    __syncthreads();

    #pragma unroll
    for (int i = 0; i < 4; ++i) {
        float inv = 1.0f / (redB[qg][0][i] + redB[qg][1][i] +
                            redB[qg][2][i] + redB[qg][3][i]);
        *(float2*)&attn_s[qg*4+i][ks] = make_float2(p[i][0]*inv, p[i][1]*inv);
    }
    // (attn_s fully written for k in [0,256): zeros beyond valid)

    // ---- Phase 2: out = attn_s @ V[b], Vs double-buffered 16-row chunks ----
    int ty = tid >> 5;          // q row 0..7
    int tx = tid & 31;          // d group of 4
    float oa[4] = {};
    int nch = (valid + 15) >> 4;          // 16-row chunks
    const float* Vp = V + (b*LK_)*D_;
    int vrow = tid >> 5;                  // 0..7 (stages rows vrow, vrow+8)
    int vcol = (tid & 31) * 4;

    float4 va = *(const float4*)(Vp + vrow*D_ + vcol);
    float4 vb = *(const float4*)(Vp + (vrow+8)*D_ + vcol);
    for (int c = 0; c < nch; ++c) {
        int buf = c & 1;
        *(float4*)&Vs[buf][vrow][vcol]   = va;
        *(float4*)&Vs[buf][vrow+8][vcol] = vb;
        if (c + 1 < 16) {                 // V always has 256 rows: safe prefetch
            const float* src = Vp + (c+1)*16*D_;
            va = *(const float4*)(src + vrow*D_ + vcol);
            vb = *(const float4*)(src + (vrow+8)*D_ + vcol);
        }
        __syncthreads();                  // first iter also orders attn_s writes
        int k0 = c * 16;
        #pragma unroll
        for (int kk = 0; kk < 16; ++kk) {
            float a = attn_s[ty][k0+kk];  // broadcast within warp
            float4 v4 = *(const float4*)&Vs[buf][kk][tx*4];
            oa[0] = fmaf(a, v4.x, oa[0]);
            oa[1] = fmaf(a, v4.y, oa[1]);
            oa[2] = fmaf(a, v4.z, oa[2]);
            oa[3] = fmaf(a, v4.w, oa[3]);
        }
    }
    float* Cp = g_CONCAT + (b*LQ_ + q0 + ty)*(NH_*D_) + n*D_ + tx*4;
    *(float4*)Cp = make_float4(oa[0], oa[1], oa[2], oa[3]);
}

// ============================================================================
// K3: split-K output projection — double-buffered, with FUSED last-block
// reduction (threadFenceReduction pattern; atomics gate readiness only,
// float summation order is fixed s=0..7 -> bit-identical to the old reduce).
// grid (8 row-tiles, 4 h-tiles, 8 splits), 256 threads.
// ============================================================================
__global__ void __launch_bounds__(256) outproj_split_kernel(
    const float* __restrict__ Wo, const float* __restrict__ bias,
    float* __restrict__ out)
{
    __shared__ float As[2][16][65];   // [buf][j][row] (scalar-read only)
    __shared__ float Bs[2][16][36];   // [buf][j][h]   (float4-read, aligned rows)
    __shared__ int is_last;
    int r0 = blockIdx.x * 64;
    int h0 = blockIdx.y * 32;
    int split = blockIdx.z;
    int j0base = split * (NH_*D_ / NSPLIT);   // 128-wide K chunk
    int tid = threadIdx.x;          // 256
    int ry = tid >> 3;              // 0..31 -> row pair
    int tx = tid & 7;               // -> h group of 4
    const float* Cc = g_CONCAT;
    float acc[2][4] = {};

    int arow = tid >> 2;            // 0..63 (A staging row)
    int ajq  = (tid & 3) * 4;       // j offset 0,4,8,12
    int bhr  = (tid & 127) >> 2;    // 0..31 (B staging h), threads 0..127 only
    int bjq  = (tid & 3) * 4;

    float4 a4 = *(const float4*)(Cc + (r0+arow)*(NH_*D_) + j0base + ajq);
    float4 w4;
    if (tid < 128) w4 = *(const float4*)(Wo + (h0+bhr)*(NH_*D_) + j0base + bjq);

    #pragma unroll
    for (int jc = 0; jc < 8; ++jc) {
        int buf = jc & 1;
        As[buf][ajq+0][arow] = a4.x; As[buf][ajq+1][arow] = a4.y;
        As[buf][ajq+2][arow] = a4.z; As[buf][ajq+3][arow] = a4.w;
        if (tid < 128) {
            Bs[buf][bjq+0][bhr] = w4.x; Bs[buf][bjq+1][bhr] = w4.y;
            Bs[buf][bjq+2][bhr] = w4.z; Bs[buf][bjq+3][bhr] = w4.w;
        }
        if (jc < 7) {
            int j0n = j0base + (jc+1) * 16;
            a4 = *(const float4*)(Cc + (r0+arow)*(NH_*D_) + j0n + ajq);
            if (tid < 128) w4 = *(const float4*)(Wo + (h0+bhr)*(NH_*D_) + j0n + bjq);
        }
        __syncthreads();
        #pragma unroll
        for (int jj = 0; jj < 16; ++jj) {
            float a0 = As[buf][jj][ry*2+0];
            float a1 = As[buf][jj][ry*2+1];
            float4 b4 = *(const float4*)&Bs[buf][jj][tx*4];
            float bv[4] = {b4.x, b4.y, b4.z, b4.w};
            #pragma unroll
            for (int j = 0; j < 4; ++j) {
                acc[0][j] = fmaf(a0, bv[j], acc[0][j]);
                acc[1][j] = fmaf(a1, bv[j], acc[1][j]);
            }
        }
    }
    float* Pp = g_PART + ((split*(B_*LQ_)) + r0 + ry*2)*H_ + h0 + tx*4;
    #pragma unroll
    for (int i = 0; i < 2; ++i)
        *(float4*)(Pp + i*H_) = make_float4(acc[i][0], acc[i][1], acc[i][2], acc[i][3]);

    // ---- last-block reduction for this (r0, h0) tile ----
    __threadfence();                       // partials visible device-wide
    __syncthreads();                       // all threads' stores + fences done
    if (tid == 0) {
        int old = atomicAdd(&g_cnt[blockIdx.x][blockIdx.y], 1);
        is_last = (old == NSPLIT - 1);
    }
    __syncthreads();
    if (is_last) {
        if (tid == 0) g_cnt[blockIdx.x][blockIdx.y] = 0;   // reset for next replay
        __threadfence();                   // acquire side
        int col = h0 + (tid & 31);
        int rb2 = r0 + (tid >> 5);         // 0..7 within tile
        float bv = bias[col];
        #pragma unroll
        for (int i = 0; i < 8; ++i) {
            int row = rb2 + i*8;
            float a = bv;
            #pragma unroll
            for (int s = 0; s < NSPLIT; ++s)
                a += g_PART[(s*(B_*LQ_) + row)*H_ + col];
            out[row*H_ + col] = a;
        }
    }
}

// ============================================================================
extern "C" void kernel_launch(void* const* d_in, const int* in_sizes, int n_in,
                              void* d_out, int out_size)
{
    const float* queries    = (const float*)d_in[0];
    const float* keys       = (const float*)d_in[1];
    const float* values     = (const float*)d_in[2];
    const int*   valid_lens = (const int*)  d_in[3];
    const float* Wq         = (const float*)d_in[4];
    const float* Wk         = (const float*)d_in[5];
    const float* wv         = (const float*)d_in[6];
    const float* Wo_w       = (const float*)d_in[7];
    const float* Wo_b       = (const float*)d_in[8];
    float* out = (float*)d_out;

    proj_kernel<<<dim3(4, 2, 48), 256>>>(queries, keys, Wq, Wk);
    score_av_kernel<<<dim3(LQ_/8, NH_, B_), 256>>>(wv, valid_lens, values);
    outproj_split_kernel<<<dim3(8, 4, NSPLIT), 256>>>(Wo_w, Wo_b, out);
}